// round 14
// baseline (speedup 1.0000x reference)
#include <cuda_runtime.h>
#include <cuda_bf16.h>
#include <cuda_fp16.h>
#include <cstdint>

#define NN 50000
#define EE 800000
#define INF 128
#define HC 128
#define HH 8
#define ED 16

#define NPAD 50176            // 196 * 256, >= NN+1
#define FE_ROWS 128           // sorted edges per fused CTA (EE % 128 == 0)

// ---- scratch (device globals; no allocation allowed) ----
__device__ __align__(16) float g_q[NN * HC];
__device__ __align__(16) __half g_kh[NN * HC];    // k in fp16
__device__ __align__(16) __half g_vh[NN * HC];    // v in fp16
__device__ __align__(16) float g_attn[NN * HC];   // unnormalized numerator
__device__ __align__(16) float g_sum[NN * HH];    // softmax denominator
__device__ int g_cnt[NPAD];        // per-dst degree histogram (zero-padded)
__device__ int g_rowptr[NPAD];     // exclusive prefix sum
__device__ int g_wcnt[NN];         // write cursors for permute
__device__ int g_blk[256];         // per-block sums for scan
__device__ __align__(16) int4 g_sde[EE];  // (src, dst, eid) sorted by dst

// bf16 hi/lo scratch (pad rows stay zero -> unguarded tile loads are safe)
__device__ __align__(16) unsigned short g_xh[NPAD * INF];
__device__ __align__(16) unsigned short g_xl[NPAD * INF];
__device__ __align__(16) unsigned short g_wh[4][HC * INF];  // [n][k] layout
__device__ __align__(16) unsigned short g_wl[4][HC * INF];

// ---------------------------------------------------------------------------
__global__ void zero_kernel() {
    int i = blockIdx.x * blockDim.x + threadIdx.x;
    if (i < NPAD) g_cnt[i] = 0;
    int n4 = (NN * HC) / 4;
    if (i < n4) ((float4*)g_attn)[i] = make_float4(0.f, 0.f, 0.f, 0.f);
    if (i < NN * HH) g_sum[i] = 0.f;
}

__global__ void hist_kernel(const int* __restrict__ ei) {
    int e = blockIdx.x * blockDim.x + threadIdx.x;
    if (e < EE) atomicAdd(&g_cnt[ei[EE + e]], 1);
}

__global__ void scan1_kernel() {
    __shared__ int s[256];
    int t = threadIdx.x;
    int i = blockIdx.x * 256 + t;
    int v = g_cnt[i];
    s[t] = v;
    __syncthreads();
    #pragma unroll
    for (int off = 1; off < 256; off <<= 1) {
        int u = (t >= off) ? s[t - off] : 0;
        __syncthreads();
        s[t] += u;
        __syncthreads();
    }
    g_rowptr[i] = s[t] - v;
    if (t == 255) g_blk[blockIdx.x] = s[255];
}

__global__ void scan2_kernel() {
    __shared__ int s[256];
    int t = threadIdx.x;
    int v = (t < 196) ? g_blk[t] : 0;
    s[t] = v;
    __syncthreads();
    #pragma unroll
    for (int off = 1; off < 256; off <<= 1) {
        int u = (t >= off) ? s[t - off] : 0;
        __syncthreads();
        s[t] += u;
        __syncthreads();
    }
    if (t < 196) g_blk[t] = s[t] - v;
}

__global__ void scan3_kernel() {
    int i = blockIdx.x * blockDim.x + threadIdx.x;
    if (i < NPAD) {
        int v = g_rowptr[i] + g_blk[i >> 8];
        g_rowptr[i] = v;
        if (i < NN) g_wcnt[i] = v;
    }
}

__global__ void permute_kernel(const int* __restrict__ ei) {
    int e = blockIdx.x * blockDim.x + threadIdx.x;
    if (e < EE) {
        int src = ei[e];
        int dst = ei[EE + e];
        int pos = atomicAdd(&g_wcnt[dst], 1);
        g_sde[pos] = make_int4(src, dst, e, 0);
    }
}

// ---------------------------------------------------------------------------
// convert x (fp32 [m][k]) -> bf16 hi/lo, same layout
// ---------------------------------------------------------------------------
__global__ void convert_x_kernel(const float* __restrict__ x) {
    int i = blockIdx.x * blockDim.x + threadIdx.x;   // float4 index
    if (i >= (NN * INF) / 4) return;
    float4 v = ((const float4*)x)[i];
    float vv[4] = {v.x, v.y, v.z, v.w};
    unsigned short h[4], l[4];
    #pragma unroll
    for (int j = 0; j < 4; j++) {
        __nv_bfloat16 hb = __float2bfloat16(vv[j]);
        __nv_bfloat16 lb = __float2bfloat16(vv[j] - __bfloat162float(hb));
        h[j] = __bfloat16_as_ushort(hb);
        l[j] = __bfloat16_as_ushort(lb);
    }
    uint2 ph = make_uint2((uint32_t)h[0] | ((uint32_t)h[1] << 16),
                          (uint32_t)h[2] | ((uint32_t)h[3] << 16));
    uint2 pl = make_uint2((uint32_t)l[0] | ((uint32_t)l[1] << 16),
                          (uint32_t)l[2] | ((uint32_t)l[3] << 16));
    ((uint2*)g_xh)[i] = ph;
    ((uint2*)g_xl)[i] = pl;
}

// ---------------------------------------------------------------------------
// convert W (fp32 [k][n]) -> bf16 hi/lo, TRANSPOSED to [n][k]
// ---------------------------------------------------------------------------
__global__ void convert_w_kernel(
    const float* __restrict__ wq, const float* __restrict__ wk,
    const float* __restrict__ wv, const float* __restrict__ ws)
{
    int m = blockIdx.y;
    const float* W = (m == 0) ? wq : (m == 1) ? wk : (m == 2) ? wv : ws;
    int idx = blockIdx.x * 256 + threadIdx.x;  // 0..16383
    int n = idx & 127, k = idx >> 7;
    float v = W[k * HC + n];
    __nv_bfloat16 hb = __float2bfloat16(v);
    __nv_bfloat16 lb = __float2bfloat16(v - __bfloat162float(hb));
    g_wh[m][n * INF + k] = __bfloat16_as_ushort(hb);
    g_wl[m][n * INF + k] = __bfloat16_as_ushort(lb);
}

// ---------------------------------------------------------------------------
// HMMA GEMM: D = x@W + b for 4 matrices, bf16 hi/lo split (3 terms).
// M-tile 64 (2 CTAs/SM, 16 warps — occupancy fix): CTA = 64x128, 8 warps
// (2x4), warp tile 32x32, m16n8k16 atoms. regs capped at 128 via
// __launch_bounds__(256,2). k/v stored fp16.
// ---------------------------------------------------------------------------
#define ASTRIDE 272          // bytes per smem row (136 bf16)
#define SM_A_H  0            // 64*272 = 17408
#define SM_A_L  17408
#define SM_B_H  34816        // 128*272 = 34816
#define SM_B_L  69632
#define SM_BIAS 104448       // 512 floats = 2048
#define SM_TOT  106496

__global__ __launch_bounds__(256, 2) void mma_gemm_kernel(
    const float* __restrict__ bq, const float* __restrict__ bk,
    const float* __restrict__ bv, const float* __restrict__ bs,
    float* __restrict__ out)
{
    extern __shared__ char sm[];
    int tid = threadIdx.x;
    int w = tid >> 5;
    int lane = tid & 31;
    int g = lane >> 2;        // 0..7
    int t = lane & 3;         // 0..3
    int mw = w >> 2;          // 0..1  (rows mw*32)
    int nw = w & 3;           // 0..3  (cols nw*32)
    int rowBase = blockIdx.x * 64;

    // ---- copy A tile (64 rows, hi+lo) from bf16 scratch ----
    #pragma unroll
    for (int i = 0; i < 4; i++) {
        int idx = tid + i * 256;          // 0..1023
        int r = idx >> 4;                 // row 0..63
        int kc = idx & 15;                // 8-bf16 chunk
        size_t src = ((size_t)(rowBase + r) * INF + kc * 8) * 2;
        *(uint4*)(sm + SM_A_H + r * ASTRIDE + kc * 16) =
            *(const uint4*)((const char*)g_xh + src);
        *(uint4*)(sm + SM_A_L + r * ASTRIDE + kc * 16) =
            *(const uint4*)((const char*)g_xl + src);
    }
    for (int j = tid; j < 512; j += 256) {
        int m = j >> 7, c = j & 127;
        const float* B = (m == 0) ? bq : (m == 1) ? bk : (m == 2) ? bv : bs;
        *(float*)(sm + SM_BIAS + j * 4) = B[c];
    }

    for (int m = 0; m < 4; m++) {
        __syncthreads();     // protect previous B from overwrite
        #pragma unroll
        for (int i = 0; i < 8; i++) {
            int idx = tid + i * 256;      // 0..2047
            int n = idx >> 4;
            int kc = idx & 15;
            size_t src = ((size_t)n * INF + kc * 8) * 2;
            *(uint4*)(sm + SM_B_H + n * ASTRIDE + kc * 16) =
                *(const uint4*)((const char*)g_wh[m] + src);
            *(uint4*)(sm + SM_B_L + n * ASTRIDE + kc * 16) =
                *(const uint4*)((const char*)g_wl[m] + src);
        }
        __syncthreads();

        float acc[2][4][4];
        #pragma unroll
        for (int a = 0; a < 2; a++)
            #pragma unroll
            for (int b = 0; b < 4; b++)
                #pragma unroll
                for (int c = 0; c < 4; c++) acc[a][b][c] = 0.f;

        #pragma unroll
        for (int s = 0; s < 3; s++) {
            const char* Ab = sm + ((s == 2) ? SM_A_L : SM_A_H);
            const char* Bb = sm + ((s == 1) ? SM_B_L : SM_B_H);
            #pragma unroll
            for (int kt = 0; kt < 8; kt++) {
                int kb = (kt * 16 + t * 2) * 2;
                uint32_t bf[4][2];
                #pragma unroll
                for (int nt = 0; nt < 4; nt++) {
                    const char* p = Bb + (nw * 32 + nt * 8 + g) * ASTRIDE + kb;
                    bf[nt][0] = *(const uint32_t*)p;
                    bf[nt][1] = *(const uint32_t*)(p + 16);
                }
                #pragma unroll
                for (int mt = 0; mt < 2; mt++) {
                    const char* p = Ab + (mw * 32 + mt * 16 + g) * ASTRIDE + kb;
                    uint32_t a0 = *(const uint32_t*)p;
                    uint32_t a1 = *(const uint32_t*)(p + 8 * ASTRIDE);
                    uint32_t a2 = *(const uint32_t*)(p + 16);
                    uint32_t a3 = *(const uint32_t*)(p + 8 * ASTRIDE + 16);
                    #pragma unroll
                    for (int nt = 0; nt < 4; nt++) {
                        asm volatile(
                            "mma.sync.aligned.m16n8k16.row.col.f32.bf16.bf16.f32 "
                            "{%0,%1,%2,%3}, {%4,%5,%6,%7}, {%8,%9}, {%0,%1,%2,%3};"
                            : "+f"(acc[mt][nt][0]), "+f"(acc[mt][nt][1]),
                              "+f"(acc[mt][nt][2]), "+f"(acc[mt][nt][3])
                            : "r"(a0), "r"(a1), "r"(a2), "r"(a3),
                              "r"(bf[nt][0]), "r"(bf[nt][1]));
                    }
                }
            }
        }

        const float* sb = (const float*)(sm + SM_BIAS) + m * 128;
        if (m == 1 || m == 2) {
            __half* O = (m == 1) ? g_kh : g_vh;
            #pragma unroll
            for (int mt = 0; mt < 2; mt++) {
                int r0 = rowBase + mw * 32 + mt * 16 + g;
                int r1 = r0 + 8;
                #pragma unroll
                for (int nt = 0; nt < 4; nt++) {
                    int col = nw * 32 + nt * 8 + t * 2;
                    float bx = sb[col], by = sb[col + 1];
                    if (r0 < NN)
                        *(__half2*)&O[(size_t)r0 * HC + col] =
                            __floats2half2_rn(acc[mt][nt][0] + bx,
                                              acc[mt][nt][1] + by);
                    if (r1 < NN)
                        *(__half2*)&O[(size_t)r1 * HC + col] =
                            __floats2half2_rn(acc[mt][nt][2] + bx,
                                              acc[mt][nt][3] + by);
                }
            }
        } else {
            float* O = (m == 0) ? g_q : out;
            #pragma unroll
            for (int mt = 0; mt < 2; mt++) {
                int r0 = rowBase + mw * 32 + mt * 16 + g;
                int r1 = r0 + 8;
                #pragma unroll
                for (int nt = 0; nt < 4; nt++) {
                    int col = nw * 32 + nt * 8 + t * 2;
                    float bx = sb[col], by = sb[col + 1];
                    if (r0 < NN) {
                        float2 o0 = make_float2(acc[mt][nt][0] + bx,
                                                acc[mt][nt][1] + by);
                        *(float2*)&O[(size_t)r0 * HC + col] = o0;
                    }
                    if (r1 < NN) {
                        float2 o1 = make_float2(acc[mt][nt][2] + bx,
                                                acc[mt][nt][3] + by);
                        *(float2*)&O[(size_t)r1 * HC + col] = o1;
                    }
                }
            }
        }
    }
}

// ---------------------------------------------------------------------------
// FUSED edge kernel. CTA = 128 dst-sorted edges.
// Phase A: e = edge_attr[eid] @ w_e via HMMA -> SMEM fp16 (no global e).
// Phase B: 8 warps x 16 sorted edges: run-length softmax accumulate + red.
// ---------------------------------------------------------------------------
__global__ __launch_bounds__(256) void fused_edge_kernel(
    const float* __restrict__ ea, const float* __restrict__ we)
{
    __shared__ unsigned short Ah[FE_ROWS * 16], Al[FE_ROWS * 16];
    __shared__ unsigned short Bh[HC * 16], Bl[HC * 16];
    __shared__ __half Esm[FE_ROWS * HC];          // 32KB

    int tid = threadIdx.x;
    int e0 = blockIdx.x * FE_ROWS;                // EE % FE_ROWS == 0

    {
        int r = tid >> 1, half = (tid & 1) * 8;
        int eid = g_sde[e0 + r].z;
        float4 v0 = *(const float4*)&ea[(size_t)eid * ED + half];
        float4 v1 = *(const float4*)&ea[(size_t)eid * ED + half + 4];
        float vv[8] = {v0.x, v0.y, v0.z, v0.w, v1.x, v1.y, v1.z, v1.w};
        #pragma unroll
        for (int j = 0; j < 8; j++) {
            __nv_bfloat16 hb = __float2bfloat16(vv[j]);
            __nv_bfloat16 lb = __float2bfloat16(vv[j] - __bfloat162float(hb));
            Ah[r * 16 + half + j] = __bfloat16_as_ushort(hb);
            Al[r * 16 + half + j] = __bfloat16_as_ushort(lb);
        }
    }
    {
        int k = tid >> 4, n0 = (tid & 15) * 8;
        #pragma unroll
        for (int j = 0; j < 8; j++) {
            float v = we[k * HC + n0 + j];
            __nv_bfloat16 hb = __float2bfloat16(v);
            __nv_bfloat16 lb = __float2bfloat16(v - __bfloat162float(hb));
            Bh[(n0 + j) * 16 + k] = __bfloat16_as_ushort(hb);
            Bl[(n0 + j) * 16 + k] = __bfloat16_as_ushort(lb);
        }
    }
    __syncthreads();

    int w = tid >> 5, lane = tid & 31;
    int g = lane >> 2, t = lane & 3;
    int mw = w >> 1, nw = w & 1;

    {
        float acc[2][8][4];
        #pragma unroll
        for (int a = 0; a < 2; a++)
            #pragma unroll
            for (int b = 0; b < 8; b++)
                #pragma unroll
                for (int c = 0; c < 4; c++) acc[a][b][c] = 0.f;

        #pragma unroll
        for (int s = 0; s < 3; s++) {
            const unsigned short* A = (s == 2) ? Al : Ah;
            const unsigned short* B = (s == 1) ? Bl : Bh;
            uint32_t bf[8][2];
            #pragma unroll
            for (int nt = 0; nt < 8; nt++) {
                const unsigned short* p = &B[(nw * 64 + nt * 8 + g) * 16 + t * 2];
                bf[nt][0] = *(const uint32_t*)p;
                bf[nt][1] = *(const uint32_t*)(p + 8);
            }
            #pragma unroll
            for (int mt = 0; mt < 2; mt++) {
                const unsigned short* p = &A[(mw * 32 + mt * 16 + g) * 16 + t * 2];
                uint32_t a0 = *(const uint32_t*)p;
                uint32_t a1 = *(const uint32_t*)(p + 8 * 16);
                uint32_t a2 = *(const uint32_t*)(p + 8);
                uint32_t a3 = *(const uint32_t*)(p + 8 * 16 + 8);
                #pragma unroll
                for (int nt = 0; nt < 8; nt++) {
                    asm volatile(
                        "mma.sync.aligned.m16n8k16.row.col.f32.bf16.bf16.f32 "
                        "{%0,%1,%2,%3}, {%4,%5,%6,%7}, {%8,%9}, {%0,%1,%2,%3};"
                        : "+f"(acc[mt][nt][0]), "+f"(acc[mt][nt][1]),
                          "+f"(acc[mt][nt][2]), "+f"(acc[mt][nt][3])
                        : "r"(a0), "r"(a1), "r"(a2), "r"(a3),
                          "r"(bf[nt][0]), "r"(bf[nt][1]));
                }
            }
        }

        #pragma unroll
        for (int mt = 0; mt < 2; mt++) {
            int r0 = mw * 32 + mt * 16 + g;
            int r1 = r0 + 8;
            #pragma unroll
            for (int nt = 0; nt < 8; nt++) {
                int col = nw * 64 + nt * 8 + t * 2;
                *(__half2*)&Esm[r0 * HC + col] =
                    __floats2half2_rn(acc[mt][nt][0], acc[mt][nt][1]);
                *(__half2*)&Esm[r1 * HC + col] =
                    __floats2half2_rn(acc[mt][nt][2], acc[mt][nt][3]);
            }
        }
    }
    __syncthreads();

    int c0 = lane << 2;
    int head = lane >> 2;
    int lbase = w * 16;
    int gbase = e0 + lbase;

    int cur_dst = -1;
    float4 q4 = make_float4(0.f, 0.f, 0.f, 0.f);
    float nx = 0.f, ny = 0.f, nz = 0.f, nw4 = 0.f, den = 0.f;

    #pragma unroll 4
    for (int i = 0; i < 16; i++) {
        int4 sde = g_sde[gbase + i];
        int src = sde.x, dst = sde.y;

        if (dst != cur_dst) {
            if (cur_dst >= 0) {
                float* op = g_attn + (size_t)cur_dst * HC + c0;
                asm volatile("red.global.add.v4.f32 [%0], {%1, %2, %3, %4};"
                             :: "l"(op), "f"(nx), "f"(ny), "f"(nz), "f"(nw4)
                             : "memory");
                if ((lane & 3) == 0) {
                    float* dp = &g_sum[cur_dst * HH + head];
                    asm volatile("red.global.add.f32 [%0], %1;"
                                 :: "l"(dp), "f"(den) : "memory");
                }
            }
            cur_dst = dst;
            q4 = *(const float4*)&g_q[(size_t)dst * HC + c0];
            nx = ny = nz = nw4 = den = 0.f;
        }

        uint2 eu = *(const uint2*)&Esm[(lbase + i) * HC + c0];
        float2 e01 = __half22float2(*reinterpret_cast<__half2*>(&eu.x));
        float2 e23 = __half22float2(*reinterpret_cast<__half2*>(&eu.y));

        uint2 ku = *(const uint2*)&g_kh[(size_t)src * HC + c0];
        float2 k01 = __half22float2(*reinterpret_cast<__half2*>(&ku.x));
        float2 k23 = __half22float2(*reinterpret_cast<__half2*>(&ku.y));

        float s = q4.x * (k01.x + e01.x) + q4.y * (k01.y + e01.y)
                + q4.z * (k23.x + e23.x) + q4.w * (k23.y + e23.y);
        s += __shfl_xor_sync(0xffffffffu, s, 1);
        s += __shfl_xor_sync(0xffffffffu, s, 2);

        float p = __expf(s * 0.25f);

        uint2 vu = *(const uint2*)&g_vh[(size_t)src * HC + c0];
        float2 v01 = __half22float2(*reinterpret_cast<__half2*>(&vu.x));
        float2 v23 = __half22float2(*reinterpret_cast<__half2*>(&vu.y));

        nx  += (v01.x + e01.x) * p;
        ny  += (v01.y + e01.y) * p;
        nz  += (v23.x + e23.x) * p;
        nw4 += (v23.y + e23.y) * p;
        den += p;
    }

    if (cur_dst >= 0) {
        float* op = g_attn + (size_t)cur_dst * HC + c0;
        asm volatile("red.global.add.v4.f32 [%0], {%1, %2, %3, %4};"
                     :: "l"(op), "f"(nx), "f"(ny), "f"(nz), "f"(nw4)
                     : "memory");
        if ((lane & 3) == 0) {
            float* dp = &g_sum[cur_dst * HH + head];
            asm volatile("red.global.add.f32 [%0], %1;"
                         :: "l"(dp), "f"(den) : "memory");
        }
    }
}

// ---------------------------------------------------------------------------
__global__ __launch_bounds__(256) void normalize_kernel(float* __restrict__ out)
{
    int i = blockIdx.x * blockDim.x + threadIdx.x;
    int n4 = (NN * HC) / 4;
    if (i >= n4) return;
    int node = i >> 5;
    int head = (i & 31) >> 2;
    float inv = 1.f / (g_sum[node * HH + head] + 1e-16f);
    float4 a = ((const float4*)g_attn)[i];
    float4 o = ((float4*)out)[i];
    o.x += a.x * inv; o.y += a.y * inv;
    o.z += a.z * inv; o.w += a.w * inv;
    ((float4*)out)[i] = o;
}

// ---------------------------------------------------------------------------
extern "C" void kernel_launch(void* const* d_in, const int* in_sizes, int n_in,
                              void* d_out, int out_size)
{
    const float* x  = (const float*)d_in[0];
    const int*   ei = (const int*)d_in[1];
    const float* ea = (const float*)d_in[2];
    const float* wq = (const float*)d_in[3];
    const float* bq = (const float*)d_in[4];
    const float* wk = (const float*)d_in[5];
    const float* bk = (const float*)d_in[6];
    const float* wv = (const float*)d_in[7];
    const float* bv = (const float*)d_in[8];
    const float* we = (const float*)d_in[9];
    const float* ws = (const float*)d_in[10];
    const float* bs = (const float*)d_in[11];
    float* out = (float*)d_out;

    static bool attr_set = false;
    if (!attr_set) {
        cudaFuncSetAttribute(mma_gemm_kernel,
                             cudaFuncAttributeMaxDynamicSharedMemorySize, SM_TOT);
        attr_set = true;
    }

    // 4th launch = ncu's captured slot -> mma_gemm
    zero_kernel<<<((NN * HC) / 4 + 255) / 256, 256>>>();
    convert_x_kernel<<<((NN * INF) / 4 + 255) / 256, 256>>>(x);
    dim3 gw(64, 4);
    convert_w_kernel<<<gw, 256>>>(wq, wk, wv, ws);
    mma_gemm_kernel<<<(NN + 63) / 64, 256, SM_TOT>>>(bq, bk, bv, bs, out);

    hist_kernel<<<(EE + 255) / 256, 256>>>(ei);
    scan1_kernel<<<196, 256>>>();
    scan2_kernel<<<1, 256>>>();
    scan3_kernel<<<NPAD / 256, 256>>>();
    permute_kernel<<<(EE + 255) / 256, 256>>>(ei);

    fused_edge_kernel<<<EE / FE_ROWS, 256>>>(ea, we);

    normalize_kernel<<<((NN * HC) / 4 + 255) / 256, 256>>>(out);
}

// round 15
// speedup vs baseline: 1.0827x; 1.0827x over previous
#include <cuda_runtime.h>
#include <cuda_bf16.h>
#include <cuda_fp16.h>
#include <cstdint>

#define NN 50000
#define EE 800000
#define INF 128
#define HC 128
#define HH 8
#define ED 16

#define NPAD 50176            // 196 * 256, >= NN+1
#define FE_ROWS 128           // sorted edges per fused CTA (EE % 128 == 0)

// ---- scratch (device globals; no allocation allowed) ----
__device__ __align__(16) float g_q[NN * HC];
__device__ __align__(16) __half g_kh[NN * HC];    // k in fp16
__device__ __align__(16) __half g_vh[NN * HC];    // v in fp16
__device__ __align__(16) float g_attn[NN * HC];   // unnormalized numerator
__device__ __align__(16) float g_sum[NN * HH];    // softmax denominator
__device__ int g_cnt[NPAD];        // per-dst degree histogram (zero-padded)
__device__ int g_rowptr[NPAD];     // exclusive prefix sum
__device__ int g_wcnt[NN];         // write cursors for permute
__device__ int g_blk[256];         // per-block sums for scan
__device__ __align__(16) int4 g_sde[EE];  // (src, dst, eid) sorted by dst

// bf16 hi/lo scratch (pad rows stay zero -> unguarded tile loads are safe)
__device__ __align__(16) unsigned short g_xh[NPAD * INF];
__device__ __align__(16) unsigned short g_xl[NPAD * INF];
__device__ __align__(16) unsigned short g_wh[4][HC * INF];  // [n][k] layout
__device__ __align__(16) unsigned short g_wl[4][HC * INF];

// ---------------------------------------------------------------------------
__global__ void zero_kernel() {
    int i = blockIdx.x * blockDim.x + threadIdx.x;
    if (i < NPAD) g_cnt[i] = 0;
    int n4 = (NN * HC) / 4;
    if (i < n4) ((float4*)g_attn)[i] = make_float4(0.f, 0.f, 0.f, 0.f);
    if (i < NN * HH) g_sum[i] = 0.f;
}

__global__ void hist_kernel(const int* __restrict__ ei) {
    int e = blockIdx.x * blockDim.x + threadIdx.x;
    if (e < EE) atomicAdd(&g_cnt[ei[EE + e]], 1);
}

__global__ void scan1_kernel() {
    __shared__ int s[256];
    int t = threadIdx.x;
    int i = blockIdx.x * 256 + t;
    int v = g_cnt[i];
    s[t] = v;
    __syncthreads();
    #pragma unroll
    for (int off = 1; off < 256; off <<= 1) {
        int u = (t >= off) ? s[t - off] : 0;
        __syncthreads();
        s[t] += u;
        __syncthreads();
    }
    g_rowptr[i] = s[t] - v;
    if (t == 255) g_blk[blockIdx.x] = s[255];
}

__global__ void scan2_kernel() {
    __shared__ int s[256];
    int t = threadIdx.x;
    int v = (t < 196) ? g_blk[t] : 0;
    s[t] = v;
    __syncthreads();
    #pragma unroll
    for (int off = 1; off < 256; off <<= 1) {
        int u = (t >= off) ? s[t - off] : 0;
        __syncthreads();
        s[t] += u;
        __syncthreads();
    }
    if (t < 196) g_blk[t] = s[t] - v;
}

__global__ void scan3_kernel() {
    int i = blockIdx.x * blockDim.x + threadIdx.x;
    if (i < NPAD) {
        int v = g_rowptr[i] + g_blk[i >> 8];
        g_rowptr[i] = v;
        if (i < NN) g_wcnt[i] = v;
    }
}

__global__ void permute_kernel(const int* __restrict__ ei) {
    int e = blockIdx.x * blockDim.x + threadIdx.x;
    if (e < EE) {
        int src = ei[e];
        int dst = ei[EE + e];
        int pos = atomicAdd(&g_wcnt[dst], 1);
        g_sde[pos] = make_int4(src, dst, e, 0);
    }
}

// ---------------------------------------------------------------------------
// convert x (fp32 [m][k]) -> bf16 hi/lo, same layout
// ---------------------------------------------------------------------------
__global__ void convert_x_kernel(const float* __restrict__ x) {
    int i = blockIdx.x * blockDim.x + threadIdx.x;   // float4 index
    if (i >= (NN * INF) / 4) return;
    float4 v = ((const float4*)x)[i];
    float vv[4] = {v.x, v.y, v.z, v.w};
    unsigned short h[4], l[4];
    #pragma unroll
    for (int j = 0; j < 4; j++) {
        __nv_bfloat16 hb = __float2bfloat16(vv[j]);
        __nv_bfloat16 lb = __float2bfloat16(vv[j] - __bfloat162float(hb));
        h[j] = __bfloat16_as_ushort(hb);
        l[j] = __bfloat16_as_ushort(lb);
    }
    uint2 ph = make_uint2((uint32_t)h[0] | ((uint32_t)h[1] << 16),
                          (uint32_t)h[2] | ((uint32_t)h[3] << 16));
    uint2 pl = make_uint2((uint32_t)l[0] | ((uint32_t)l[1] << 16),
                          (uint32_t)l[2] | ((uint32_t)l[3] << 16));
    ((uint2*)g_xh)[i] = ph;
    ((uint2*)g_xl)[i] = pl;
}

// ---------------------------------------------------------------------------
// convert W (fp32 [k][n]) -> bf16 hi/lo, TRANSPOSED to [n][k]
// ---------------------------------------------------------------------------
__global__ void convert_w_kernel(
    const float* __restrict__ wq, const float* __restrict__ wk,
    const float* __restrict__ wv, const float* __restrict__ ws)
{
    int m = blockIdx.y;
    const float* W = (m == 0) ? wq : (m == 1) ? wk : (m == 2) ? wv : ws;
    int idx = blockIdx.x * 256 + threadIdx.x;  // 0..16383
    int n = idx & 127, k = idx >> 7;
    float v = W[k * HC + n];
    __nv_bfloat16 hb = __float2bfloat16(v);
    __nv_bfloat16 lb = __float2bfloat16(v - __bfloat162float(hb));
    g_wh[m][n * INF + k] = __bfloat16_as_ushort(hb);
    g_wl[m][n * INF + k] = __bfloat16_as_ushort(lb);
}

// ---------------------------------------------------------------------------
// HMMA GEMM: D = x@W + b for 4 matrices, bf16 hi/lo split (3 terms).
// CTA = 128x128 (R13 geometry), 8 warps (2x4), warp tile 64x32.
// LDS-port fix: A-hi fragments loaded ONCE per kt and reused for both
// Bh and Bl terms (72 -> 56 LDS.32 per kt). k/v stored fp16.
// ---------------------------------------------------------------------------
#define ASTRIDE 272          // bytes per smem row (136 bf16)
#define SM_A_H  0            // 128*272 = 34816
#define SM_A_L  34816
#define SM_B_H  69632
#define SM_B_L  104448
#define SM_BIAS 139264       // 512 floats = 2048
#define SM_TOT  141312

__global__ __launch_bounds__(256, 1) void mma_gemm_kernel(
    const float* __restrict__ bq, const float* __restrict__ bk,
    const float* __restrict__ bv, const float* __restrict__ bs,
    float* __restrict__ out)
{
    extern __shared__ char sm[];
    int tid = threadIdx.x;
    int w = tid >> 5;
    int lane = tid & 31;
    int g = lane >> 2;        // 0..7
    int t = lane & 3;         // 0..3
    int mw = w >> 2;          // 0..1
    int nw = w & 3;           // 0..3
    int rowBase = blockIdx.x * 128;

    #pragma unroll
    for (int i = 0; i < 8; i++) {
        int idx = tid + i * 256;          // 0..2047
        int r = idx >> 4;                 // row 0..127
        int kc = idx & 15;                // 8-bf16 chunk
        size_t src = ((size_t)(rowBase + r) * INF + kc * 8) * 2;
        *(uint4*)(sm + SM_A_H + r * ASTRIDE + kc * 16) =
            *(const uint4*)((const char*)g_xh + src);
        *(uint4*)(sm + SM_A_L + r * ASTRIDE + kc * 16) =
            *(const uint4*)((const char*)g_xl + src);
    }
    for (int j = tid; j < 512; j += 256) {
        int m = j >> 7, c = j & 127;
        const float* B = (m == 0) ? bq : (m == 1) ? bk : (m == 2) ? bv : bs;
        *(float*)(sm + SM_BIAS + j * 4) = B[c];
    }

    for (int m = 0; m < 4; m++) {
        __syncthreads();     // protect previous B from overwrite
        #pragma unroll
        for (int i = 0; i < 8; i++) {
            int idx = tid + i * 256;
            int n = idx >> 4;
            int kc = idx & 15;
            size_t src = ((size_t)n * INF + kc * 8) * 2;
            *(uint4*)(sm + SM_B_H + n * ASTRIDE + kc * 16) =
                *(const uint4*)((const char*)g_wh[m] + src);
            *(uint4*)(sm + SM_B_L + n * ASTRIDE + kc * 16) =
                *(const uint4*)((const char*)g_wl[m] + src);
        }
        __syncthreads();

        float acc[4][4][4];
        #pragma unroll
        for (int a = 0; a < 4; a++)
            #pragma unroll
            for (int b = 0; b < 4; b++)
                #pragma unroll
                for (int c = 0; c < 4; c++) acc[a][b][c] = 0.f;

        // ---- pass 1: A-hi loaded once per kt, MMA vs Bh then Bl ----
        #pragma unroll
        for (int kt = 0; kt < 8; kt++) {
            int kb = (kt * 16 + t * 2) * 2;
            uint32_t af[4][4];
            #pragma unroll
            for (int mt = 0; mt < 4; mt++) {
                const char* p = sm + SM_A_H + (mw * 64 + mt * 16 + g) * ASTRIDE + kb;
                af[mt][0] = *(const uint32_t*)p;
                af[mt][1] = *(const uint32_t*)(p + 8 * ASTRIDE);
                af[mt][2] = *(const uint32_t*)(p + 16);
                af[mt][3] = *(const uint32_t*)(p + 8 * ASTRIDE + 16);
            }
            #pragma unroll
            for (int sb2 = 0; sb2 < 2; sb2++) {
                const char* Bb = sm + (sb2 ? SM_B_L : SM_B_H);
                #pragma unroll
                for (int nt = 0; nt < 4; nt++) {
                    const char* p = Bb + (nw * 32 + nt * 8 + g) * ASTRIDE + kb;
                    uint32_t b0 = *(const uint32_t*)p;
                    uint32_t b1 = *(const uint32_t*)(p + 16);
                    #pragma unroll
                    for (int mt = 0; mt < 4; mt++) {
                        asm volatile(
                            "mma.sync.aligned.m16n8k16.row.col.f32.bf16.bf16.f32 "
                            "{%0,%1,%2,%3}, {%4,%5,%6,%7}, {%8,%9}, {%0,%1,%2,%3};"
                            : "+f"(acc[mt][nt][0]), "+f"(acc[mt][nt][1]),
                              "+f"(acc[mt][nt][2]), "+f"(acc[mt][nt][3])
                            : "r"(af[mt][0]), "r"(af[mt][1]),
                              "r"(af[mt][2]), "r"(af[mt][3]),
                              "r"(b0), "r"(b1));
                    }
                }
            }
        }
        // ---- pass 2: A-lo vs Bh ----
        #pragma unroll
        for (int kt = 0; kt < 8; kt++) {
            int kb = (kt * 16 + t * 2) * 2;
            uint32_t bf[4][2];
            #pragma unroll
            for (int nt = 0; nt < 4; nt++) {
                const char* p = sm + SM_B_H + (nw * 32 + nt * 8 + g) * ASTRIDE + kb;
                bf[nt][0] = *(const uint32_t*)p;
                bf[nt][1] = *(const uint32_t*)(p + 16);
            }
            #pragma unroll
            for (int mt = 0; mt < 4; mt++) {
                const char* p = sm + SM_A_L + (mw * 64 + mt * 16 + g) * ASTRIDE + kb;
                uint32_t a0 = *(const uint32_t*)p;
                uint32_t a1 = *(const uint32_t*)(p + 8 * ASTRIDE);
                uint32_t a2 = *(const uint32_t*)(p + 16);
                uint32_t a3 = *(const uint32_t*)(p + 8 * ASTRIDE + 16);
                #pragma unroll
                for (int nt = 0; nt < 4; nt++) {
                    asm volatile(
                        "mma.sync.aligned.m16n8k16.row.col.f32.bf16.bf16.f32 "
                        "{%0,%1,%2,%3}, {%4,%5,%6,%7}, {%8,%9}, {%0,%1,%2,%3};"
                        : "+f"(acc[mt][nt][0]), "+f"(acc[mt][nt][1]),
                          "+f"(acc[mt][nt][2]), "+f"(acc[mt][nt][3])
                        : "r"(a0), "r"(a1), "r"(a2), "r"(a3),
                          "r"(bf[nt][0]), "r"(bf[nt][1]));
                }
            }
        }

        const float* sb = (const float*)(sm + SM_BIAS) + m * 128;
        if (m == 1 || m == 2) {
            __half* O = (m == 1) ? g_kh : g_vh;
            #pragma unroll
            for (int mt = 0; mt < 4; mt++) {
                int r0 = rowBase + mw * 64 + mt * 16 + g;
                int r1 = r0 + 8;
                #pragma unroll
                for (int nt = 0; nt < 4; nt++) {
                    int col = nw * 32 + nt * 8 + t * 2;
                    float bx = sb[col], by = sb[col + 1];
                    if (r0 < NN)
                        *(__half2*)&O[(size_t)r0 * HC + col] =
                            __floats2half2_rn(acc[mt][nt][0] + bx,
                                              acc[mt][nt][1] + by);
                    if (r1 < NN)
                        *(__half2*)&O[(size_t)r1 * HC + col] =
                            __floats2half2_rn(acc[mt][nt][2] + bx,
                                              acc[mt][nt][3] + by);
                }
            }
        } else {
            float* O = (m == 0) ? g_q : out;
            #pragma unroll
            for (int mt = 0; mt < 4; mt++) {
                int r0 = rowBase + mw * 64 + mt * 16 + g;
                int r1 = r0 + 8;
                #pragma unroll
                for (int nt = 0; nt < 4; nt++) {
                    int col = nw * 32 + nt * 8 + t * 2;
                    float bx = sb[col], by = sb[col + 1];
                    if (r0 < NN) {
                        float2 o0 = make_float2(acc[mt][nt][0] + bx,
                                                acc[mt][nt][1] + by);
                        *(float2*)&O[(size_t)r0 * HC + col] = o0;
                    }
                    if (r1 < NN) {
                        float2 o1 = make_float2(acc[mt][nt][2] + bx,
                                                acc[mt][nt][3] + by);
                        *(float2*)&O[(size_t)r1 * HC + col] = o1;
                    }
                }
            }
        }
    }
}

// ---------------------------------------------------------------------------
// FUSED edge kernel. CTA = 128 dst-sorted edges. (R13-proven, unchanged)
// ---------------------------------------------------------------------------
__global__ __launch_bounds__(256) void fused_edge_kernel(
    const float* __restrict__ ea, const float* __restrict__ we)
{
    __shared__ unsigned short Ah[FE_ROWS * 16], Al[FE_ROWS * 16];
    __shared__ unsigned short Bh[HC * 16], Bl[HC * 16];
    __shared__ __half Esm[FE_ROWS * HC];          // 32KB

    int tid = threadIdx.x;
    int e0 = blockIdx.x * FE_ROWS;                // EE % FE_ROWS == 0

    {
        int r = tid >> 1, half = (tid & 1) * 8;
        int eid = g_sde[e0 + r].z;
        float4 v0 = *(const float4*)&ea[(size_t)eid * ED + half];
        float4 v1 = *(const float4*)&ea[(size_t)eid * ED + half + 4];
        float vv[8] = {v0.x, v0.y, v0.z, v0.w, v1.x, v1.y, v1.z, v1.w};
        #pragma unroll
        for (int j = 0; j < 8; j++) {
            __nv_bfloat16 hb = __float2bfloat16(vv[j]);
            __nv_bfloat16 lb = __float2bfloat16(vv[j] - __bfloat162float(hb));
            Ah[r * 16 + half + j] = __bfloat16_as_ushort(hb);
            Al[r * 16 + half + j] = __bfloat16_as_ushort(lb);
        }
    }
    {
        int k = tid >> 4, n0 = (tid & 15) * 8;
        #pragma unroll
        for (int j = 0; j < 8; j++) {
            float v = we[k * HC + n0 + j];
            __nv_bfloat16 hb = __float2bfloat16(v);
            __nv_bfloat16 lb = __float2bfloat16(v - __bfloat162float(hb));
            Bh[(n0 + j) * 16 + k] = __bfloat16_as_ushort(hb);
            Bl[(n0 + j) * 16 + k] = __bfloat16_as_ushort(lb);
        }
    }
    __syncthreads();

    int w = tid >> 5, lane = tid & 31;
    int g = lane >> 2, t = lane & 3;
    int mw = w >> 1, nw = w & 1;

    {
        float acc[2][8][4];
        #pragma unroll
        for (int a = 0; a < 2; a++)
            #pragma unroll
            for (int b = 0; b < 8; b++)
                #pragma unroll
                for (int c = 0; c < 4; c++) acc[a][b][c] = 0.f;

        #pragma unroll
        for (int s = 0; s < 3; s++) {
            const unsigned short* A = (s == 2) ? Al : Ah;
            const unsigned short* B = (s == 1) ? Bl : Bh;
            uint32_t bf[8][2];
            #pragma unroll
            for (int nt = 0; nt < 8; nt++) {
                const unsigned short* p = &B[(nw * 64 + nt * 8 + g) * 16 + t * 2];
                bf[nt][0] = *(const uint32_t*)p;
                bf[nt][1] = *(const uint32_t*)(p + 8);
            }
            #pragma unroll
            for (int mt = 0; mt < 2; mt++) {
                const unsigned short* p = &A[(mw * 32 + mt * 16 + g) * 16 + t * 2];
                uint32_t a0 = *(const uint32_t*)p;
                uint32_t a1 = *(const uint32_t*)(p + 8 * 16);
                uint32_t a2 = *(const uint32_t*)(p + 8);
                uint32_t a3 = *(const uint32_t*)(p + 8 * 16 + 8);
                #pragma unroll
                for (int nt = 0; nt < 8; nt++) {
                    asm volatile(
                        "mma.sync.aligned.m16n8k16.row.col.f32.bf16.bf16.f32 "
                        "{%0,%1,%2,%3}, {%4,%5,%6,%7}, {%8,%9}, {%0,%1,%2,%3};"
                        : "+f"(acc[mt][nt][0]), "+f"(acc[mt][nt][1]),
                          "+f"(acc[mt][nt][2]), "+f"(acc[mt][nt][3])
                        : "r"(a0), "r"(a1), "r"(a2), "r"(a3),
                          "r"(bf[nt][0]), "r"(bf[nt][1]));
                }
            }
        }

        #pragma unroll
        for (int mt = 0; mt < 2; mt++) {
            int r0 = mw * 32 + mt * 16 + g;
            int r1 = r0 + 8;
            #pragma unroll
            for (int nt = 0; nt < 8; nt++) {
                int col = nw * 64 + nt * 8 + t * 2;
                *(__half2*)&Esm[r0 * HC + col] =
                    __floats2half2_rn(acc[mt][nt][0], acc[mt][nt][1]);
                *(__half2*)&Esm[r1 * HC + col] =
                    __floats2half2_rn(acc[mt][nt][2], acc[mt][nt][3]);
            }
        }
    }
    __syncthreads();

    int c0 = lane << 2;
    int head = lane >> 2;
    int lbase = w * 16;
    int gbase = e0 + lbase;

    int cur_dst = -1;
    float4 q4 = make_float4(0.f, 0.f, 0.f, 0.f);
    float nx = 0.f, ny = 0.f, nz = 0.f, nw4 = 0.f, den = 0.f;

    #pragma unroll 4
    for (int i = 0; i < 16; i++) {
        int4 sde = g_sde[gbase + i];
        int src = sde.x, dst = sde.y;

        if (dst != cur_dst) {
            if (cur_dst >= 0) {
                float* op = g_attn + (size_t)cur_dst * HC + c0;
                asm volatile("red.global.add.v4.f32 [%0], {%1, %2, %3, %4};"
                             :: "l"(op), "f"(nx), "f"(ny), "f"(nz), "f"(nw4)
                             : "memory");
                if ((lane & 3) == 0) {
                    float* dp = &g_sum[cur_dst * HH + head];
                    asm volatile("red.global.add.f32 [%0], %1;"
                                 :: "l"(dp), "f"(den) : "memory");
                }
            }
            cur_dst = dst;
            q4 = *(const float4*)&g_q[(size_t)dst * HC + c0];
            nx = ny = nz = nw4 = den = 0.f;
        }

        uint2 eu = *(const uint2*)&Esm[(lbase + i) * HC + c0];
        float2 e01 = __half22float2(*reinterpret_cast<__half2*>(&eu.x));
        float2 e23 = __half22float2(*reinterpret_cast<__half2*>(&eu.y));

        uint2 ku = *(const uint2*)&g_kh[(size_t)src * HC + c0];
        float2 k01 = __half22float2(*reinterpret_cast<__half2*>(&ku.x));
        float2 k23 = __half22float2(*reinterpret_cast<__half2*>(&ku.y));

        float s = q4.x * (k01.x + e01.x) + q4.y * (k01.y + e01.y)
                + q4.z * (k23.x + e23.x) + q4.w * (k23.y + e23.y);
        s += __shfl_xor_sync(0xffffffffu, s, 1);
        s += __shfl_xor_sync(0xffffffffu, s, 2);

        float p = __expf(s * 0.25f);

        uint2 vu = *(const uint2*)&g_vh[(size_t)src * HC + c0];
        float2 v01 = __half22float2(*reinterpret_cast<__half2*>(&vu.x));
        float2 v23 = __half22float2(*reinterpret_cast<__half2*>(&vu.y));

        nx  += (v01.x + e01.x) * p;
        ny  += (v01.y + e01.y) * p;
        nz  += (v23.x + e23.x) * p;
        nw4 += (v23.y + e23.y) * p;
        den += p;
    }

    if (cur_dst >= 0) {
        float* op = g_attn + (size_t)cur_dst * HC + c0;
        asm volatile("red.global.add.v4.f32 [%0], {%1, %2, %3, %4};"
                     :: "l"(op), "f"(nx), "f"(ny), "f"(nz), "f"(nw4)
                     : "memory");
        if ((lane & 3) == 0) {
            float* dp = &g_sum[cur_dst * HH + head];
            asm volatile("red.global.add.f32 [%0], %1;"
                         :: "l"(dp), "f"(den) : "memory");
        }
    }
}

// ---------------------------------------------------------------------------
__global__ __launch_bounds__(256) void normalize_kernel(float* __restrict__ out)
{
    int i = blockIdx.x * blockDim.x + threadIdx.x;
    int n4 = (NN * HC) / 4;
    if (i >= n4) return;
    int node = i >> 5;
    int head = (i & 31) >> 2;
    float inv = 1.f / (g_sum[node * HH + head] + 1e-16f);
    float4 a = ((const float4*)g_attn)[i];
    float4 o = ((float4*)out)[i];
    o.x += a.x * inv; o.y += a.y * inv;
    o.z += a.z * inv; o.w += a.w * inv;
    ((float4*)out)[i] = o;
}

// ---------------------------------------------------------------------------
extern "C" void kernel_launch(void* const* d_in, const int* in_sizes, int n_in,
                              void* d_out, int out_size)
{
    const float* x  = (const float*)d_in[0];
    const int*   ei = (const int*)d_in[1];
    const float* ea = (const float*)d_in[2];
    const float* wq = (const float*)d_in[3];
    const float* bq = (const float*)d_in[4];
    const float* wk = (const float*)d_in[5];
    const float* bk = (const float*)d_in[6];
    const float* wv = (const float*)d_in[7];
    const float* bv = (const float*)d_in[8];
    const float* we = (const float*)d_in[9];
    const float* ws = (const float*)d_in[10];
    const float* bs = (const float*)d_in[11];
    float* out = (float*)d_out;

    static bool attr_set = false;
    if (!attr_set) {
        cudaFuncSetAttribute(mma_gemm_kernel,
                             cudaFuncAttributeMaxDynamicSharedMemorySize, SM_TOT);
        attr_set = true;
    }

    // 4th launch = ncu's captured slot -> mma_gemm
    zero_kernel<<<((NN * HC) / 4 + 255) / 256, 256>>>();
    convert_x_kernel<<<((NN * INF) / 4 + 255) / 256, 256>>>(x);
    dim3 gw(64, 4);
    convert_w_kernel<<<gw, 256>>>(wq, wk, wv, ws);
    mma_gemm_kernel<<<391, 256, SM_TOT>>>(bq, bk, bv, bs, out);   // 4th: profiled

    hist_kernel<<<(EE + 255) / 256, 256>>>(ei);
    scan1_kernel<<<196, 256>>>();
    scan2_kernel<<<1, 256>>>();
    scan3_kernel<<<NPAD / 256, 256>>>();
    permute_kernel<<<(EE + 255) / 256, 256>>>(ei);

    fused_edge_kernel<<<EE / FE_ROWS, 256>>>(ea, we);

    normalize_kernel<<<((NN * HC) / 4 + 255) / 256, 256>>>(out);
}

// round 16
// speedup vs baseline: 1.1505x; 1.0626x over previous
#include <cuda_runtime.h>
#include <cuda_bf16.h>
#include <cuda_fp16.h>
#include <cstdint>

#define NN 50000
#define EE 800000
#define INF 128
#define HC 128
#define HH 8
#define ED 16

#define NPAD 50176            // 196 * 256, >= NN+1
#define FE_ROWS 128           // sorted edges per fused CTA (EE % 128 == 0)

// ---- scratch (device globals; no allocation allowed) ----
__device__ __align__(16) float g_q[NN * HC];
__device__ __align__(16) __half g_kh[NN * HC];    // k in fp16
__device__ __align__(16) __half g_vh[NN * HC];    // v in fp16
__device__ __align__(16) float g_attn[NN * HC];   // unnormalized numerator
__device__ __align__(16) float g_sum[NN * HH];    // softmax denominator
__device__ int g_cnt[NPAD];        // per-dst degree histogram (zero-padded)
__device__ int g_rowptr[NPAD];     // exclusive prefix sum
__device__ int g_wcnt[NN];         // write cursors for permute
__device__ int g_blk[256];         // per-block sums for scan
__device__ __align__(16) int4 g_sde[EE];  // (src, dst, eid) sorted by dst

// bf16 hi/lo scratch (pad rows stay zero -> unguarded tile loads are safe)
__device__ __align__(16) unsigned short g_xh[NPAD * INF];
__device__ __align__(16) unsigned short g_xl[NPAD * INF];
__device__ __align__(16) unsigned short g_wh[4][HC * INF];  // [n][k] layout
__device__ __align__(16) unsigned short g_wl[4][HC * INF];

// ---------------------------------------------------------------------------
__global__ void zero_kernel() {
    int i = blockIdx.x * blockDim.x + threadIdx.x;
    if (i < NPAD) g_cnt[i] = 0;
    int n4 = (NN * HC) / 4;
    if (i < n4) ((float4*)g_attn)[i] = make_float4(0.f, 0.f, 0.f, 0.f);
    if (i < NN * HH) g_sum[i] = 0.f;
}

__global__ void hist_kernel(const int* __restrict__ ei) {
    int e = blockIdx.x * blockDim.x + threadIdx.x;
    if (e < EE) atomicAdd(&g_cnt[ei[EE + e]], 1);
}

__global__ void scan1_kernel() {
    __shared__ int s[256];
    int t = threadIdx.x;
    int i = blockIdx.x * 256 + t;
    int v = g_cnt[i];
    s[t] = v;
    __syncthreads();
    #pragma unroll
    for (int off = 1; off < 256; off <<= 1) {
        int u = (t >= off) ? s[t - off] : 0;
        __syncthreads();
        s[t] += u;
        __syncthreads();
    }
    g_rowptr[i] = s[t] - v;
    if (t == 255) g_blk[blockIdx.x] = s[255];
}

__global__ void scan2_kernel() {
    __shared__ int s[256];
    int t = threadIdx.x;
    int v = (t < 196) ? g_blk[t] : 0;
    s[t] = v;
    __syncthreads();
    #pragma unroll
    for (int off = 1; off < 256; off <<= 1) {
        int u = (t >= off) ? s[t - off] : 0;
        __syncthreads();
        s[t] += u;
        __syncthreads();
    }
    if (t < 196) g_blk[t] = s[t] - v;
}

__global__ void scan3_kernel() {
    int i = blockIdx.x * blockDim.x + threadIdx.x;
    if (i < NPAD) {
        int v = g_rowptr[i] + g_blk[i >> 8];
        g_rowptr[i] = v;
        if (i < NN) g_wcnt[i] = v;
    }
}

__global__ void permute_kernel(const int* __restrict__ ei) {
    int e = blockIdx.x * blockDim.x + threadIdx.x;
    if (e < EE) {
        int src = ei[e];
        int dst = ei[EE + e];
        int pos = atomicAdd(&g_wcnt[dst], 1);
        g_sde[pos] = make_int4(src, dst, e, 0);
    }
}

// ---------------------------------------------------------------------------
// convert x (fp32 [m][k]) -> bf16 hi/lo, same layout
// ---------------------------------------------------------------------------
__global__ void convert_x_kernel(const float* __restrict__ x) {
    int i = blockIdx.x * blockDim.x + threadIdx.x;   // float4 index
    if (i >= (NN * INF) / 4) return;
    float4 v = ((const float4*)x)[i];
    float vv[4] = {v.x, v.y, v.z, v.w};
    unsigned short h[4], l[4];
    #pragma unroll
    for (int j = 0; j < 4; j++) {
        __nv_bfloat16 hb = __float2bfloat16(vv[j]);
        __nv_bfloat16 lb = __float2bfloat16(vv[j] - __bfloat162float(hb));
        h[j] = __bfloat16_as_ushort(hb);
        l[j] = __bfloat16_as_ushort(lb);
    }
    uint2 ph = make_uint2((uint32_t)h[0] | ((uint32_t)h[1] << 16),
                          (uint32_t)h[2] | ((uint32_t)h[3] << 16));
    uint2 pl = make_uint2((uint32_t)l[0] | ((uint32_t)l[1] << 16),
                          (uint32_t)l[2] | ((uint32_t)l[3] << 16));
    ((uint2*)g_xh)[i] = ph;
    ((uint2*)g_xl)[i] = pl;
}

// ---------------------------------------------------------------------------
// convert W (fp32 [k][n]) -> bf16 hi/lo, TRANSPOSED to [n][k]
// ---------------------------------------------------------------------------
__global__ void convert_w_kernel(
    const float* __restrict__ wq, const float* __restrict__ wk,
    const float* __restrict__ wv, const float* __restrict__ ws)
{
    int m = blockIdx.y;
    const float* W = (m == 0) ? wq : (m == 1) ? wk : (m == 2) ? wv : ws;
    int idx = blockIdx.x * 256 + threadIdx.x;  // 0..16383
    int n = idx & 127, k = idx >> 7;
    float v = W[k * HC + n];
    __nv_bfloat16 hb = __float2bfloat16(v);
    __nv_bfloat16 lb = __float2bfloat16(v - __bfloat162float(hb));
    g_wh[m][n * INF + k] = __bfloat16_as_ushort(hb);
    g_wl[m][n * INF + k] = __bfloat16_as_ushort(lb);
}

// ---------------------------------------------------------------------------
// HMMA GEMM: D = x@W + b for 4 matrices, bf16 hi/lo split (3 terms).
// CTA = 128x128, 8 warps (2x4), warp tile 64x32. A-hi fragments reused
// across Bh/Bl (R15). k/v stored fp16.
// ---------------------------------------------------------------------------
#define ASTRIDE 272          // bytes per smem row (136 bf16)
#define SM_A_H  0            // 128*272 = 34816
#define SM_A_L  34816
#define SM_B_H  69632
#define SM_B_L  104448
#define SM_BIAS 139264       // 512 floats = 2048
#define SM_TOT  141312

__global__ __launch_bounds__(256, 1) void mma_gemm_kernel(
    const float* __restrict__ bq, const float* __restrict__ bk,
    const float* __restrict__ bv, const float* __restrict__ bs,
    float* __restrict__ out)
{
    extern __shared__ char sm[];
    int tid = threadIdx.x;
    int w = tid >> 5;
    int lane = tid & 31;
    int g = lane >> 2;        // 0..7
    int t = lane & 3;         // 0..3
    int mw = w >> 2;          // 0..1
    int nw = w & 3;           // 0..3
    int rowBase = blockIdx.x * 128;

    #pragma unroll
    for (int i = 0; i < 8; i++) {
        int idx = tid + i * 256;          // 0..2047
        int r = idx >> 4;                 // row 0..127
        int kc = idx & 15;                // 8-bf16 chunk
        size_t src = ((size_t)(rowBase + r) * INF + kc * 8) * 2;
        *(uint4*)(sm + SM_A_H + r * ASTRIDE + kc * 16) =
            *(const uint4*)((const char*)g_xh + src);
        *(uint4*)(sm + SM_A_L + r * ASTRIDE + kc * 16) =
            *(const uint4*)((const char*)g_xl + src);
    }
    for (int j = tid; j < 512; j += 256) {
        int m = j >> 7, c = j & 127;
        const float* B = (m == 0) ? bq : (m == 1) ? bk : (m == 2) ? bv : bs;
        *(float*)(sm + SM_BIAS + j * 4) = B[c];
    }

    for (int m = 0; m < 4; m++) {
        __syncthreads();     // protect previous B from overwrite
        #pragma unroll
        for (int i = 0; i < 8; i++) {
            int idx = tid + i * 256;
            int n = idx >> 4;
            int kc = idx & 15;
            size_t src = ((size_t)n * INF + kc * 8) * 2;
            *(uint4*)(sm + SM_B_H + n * ASTRIDE + kc * 16) =
                *(const uint4*)((const char*)g_wh[m] + src);
            *(uint4*)(sm + SM_B_L + n * ASTRIDE + kc * 16) =
                *(const uint4*)((const char*)g_wl[m] + src);
        }
        __syncthreads();

        float acc[4][4][4];
        #pragma unroll
        for (int a = 0; a < 4; a++)
            #pragma unroll
            for (int b = 0; b < 4; b++)
                #pragma unroll
                for (int c = 0; c < 4; c++) acc[a][b][c] = 0.f;

        // ---- pass 1: A-hi loaded once per kt, MMA vs Bh then Bl ----
        #pragma unroll
        for (int kt = 0; kt < 8; kt++) {
            int kb = (kt * 16 + t * 2) * 2;
            uint32_t af[4][4];
            #pragma unroll
            for (int mt = 0; mt < 4; mt++) {
                const char* p = sm + SM_A_H + (mw * 64 + mt * 16 + g) * ASTRIDE + kb;
                af[mt][0] = *(const uint32_t*)p;
                af[mt][1] = *(const uint32_t*)(p + 8 * ASTRIDE);
                af[mt][2] = *(const uint32_t*)(p + 16);
                af[mt][3] = *(const uint32_t*)(p + 8 * ASTRIDE + 16);
            }
            #pragma unroll
            for (int sb2 = 0; sb2 < 2; sb2++) {
                const char* Bb = sm + (sb2 ? SM_B_L : SM_B_H);
                #pragma unroll
                for (int nt = 0; nt < 4; nt++) {
                    const char* p = Bb + (nw * 32 + nt * 8 + g) * ASTRIDE + kb;
                    uint32_t b0 = *(const uint32_t*)p;
                    uint32_t b1 = *(const uint32_t*)(p + 16);
                    #pragma unroll
                    for (int mt = 0; mt < 4; mt++) {
                        asm volatile(
                            "mma.sync.aligned.m16n8k16.row.col.f32.bf16.bf16.f32 "
                            "{%0,%1,%2,%3}, {%4,%5,%6,%7}, {%8,%9}, {%0,%1,%2,%3};"
                            : "+f"(acc[mt][nt][0]), "+f"(acc[mt][nt][1]),
                              "+f"(acc[mt][nt][2]), "+f"(acc[mt][nt][3])
                            : "r"(af[mt][0]), "r"(af[mt][1]),
                              "r"(af[mt][2]), "r"(af[mt][3]),
                              "r"(b0), "r"(b1));
                    }
                }
            }
        }
        // ---- pass 2: A-lo vs Bh ----
        #pragma unroll
        for (int kt = 0; kt < 8; kt++) {
            int kb = (kt * 16 + t * 2) * 2;
            uint32_t bf[4][2];
            #pragma unroll
            for (int nt = 0; nt < 4; nt++) {
                const char* p = sm + SM_B_H + (nw * 32 + nt * 8 + g) * ASTRIDE + kb;
                bf[nt][0] = *(const uint32_t*)p;
                bf[nt][1] = *(const uint32_t*)(p + 16);
            }
            #pragma unroll
            for (int mt = 0; mt < 4; mt++) {
                const char* p = sm + SM_A_L + (mw * 64 + mt * 16 + g) * ASTRIDE + kb;
                uint32_t a0 = *(const uint32_t*)p;
                uint32_t a1 = *(const uint32_t*)(p + 8 * ASTRIDE);
                uint32_t a2 = *(const uint32_t*)(p + 16);
                uint32_t a3 = *(const uint32_t*)(p + 8 * ASTRIDE + 16);
                #pragma unroll
                for (int nt = 0; nt < 4; nt++) {
                    asm volatile(
                        "mma.sync.aligned.m16n8k16.row.col.f32.bf16.bf16.f32 "
                        "{%0,%1,%2,%3}, {%4,%5,%6,%7}, {%8,%9}, {%0,%1,%2,%3};"
                        : "+f"(acc[mt][nt][0]), "+f"(acc[mt][nt][1]),
                          "+f"(acc[mt][nt][2]), "+f"(acc[mt][nt][3])
                        : "r"(a0), "r"(a1), "r"(a2), "r"(a3),
                          "r"(bf[nt][0]), "r"(bf[nt][1]));
                }
            }
        }

        const float* sb = (const float*)(sm + SM_BIAS) + m * 128;
        if (m == 1 || m == 2) {
            __half* O = (m == 1) ? g_kh : g_vh;
            #pragma unroll
            for (int mt = 0; mt < 4; mt++) {
                int r0 = rowBase + mw * 64 + mt * 16 + g;
                int r1 = r0 + 8;
                #pragma unroll
                for (int nt = 0; nt < 4; nt++) {
                    int col = nw * 32 + nt * 8 + t * 2;
                    float bx = sb[col], by = sb[col + 1];
                    if (r0 < NN)
                        *(__half2*)&O[(size_t)r0 * HC + col] =
                            __floats2half2_rn(acc[mt][nt][0] + bx,
                                              acc[mt][nt][1] + by);
                    if (r1 < NN)
                        *(__half2*)&O[(size_t)r1 * HC + col] =
                            __floats2half2_rn(acc[mt][nt][2] + bx,
                                              acc[mt][nt][3] + by);
                }
            }
        } else {
            float* O = (m == 0) ? g_q : out;
            #pragma unroll
            for (int mt = 0; mt < 4; mt++) {
                int r0 = rowBase + mw * 64 + mt * 16 + g;
                int r1 = r0 + 8;
                #pragma unroll
                for (int nt = 0; nt < 4; nt++) {
                    int col = nw * 32 + nt * 8 + t * 2;
                    float bx = sb[col], by = sb[col + 1];
                    if (r0 < NN) {
                        float2 o0 = make_float2(acc[mt][nt][0] + bx,
                                                acc[mt][nt][1] + by);
                        *(float2*)&O[(size_t)r0 * HC + col] = o0;
                    }
                    if (r1 < NN) {
                        float2 o1 = make_float2(acc[mt][nt][2] + bx,
                                                acc[mt][nt][3] + by);
                        *(float2*)&O[(size_t)r1 * HC + col] = o1;
                    }
                }
            }
        }
    }
}

// ---------------------------------------------------------------------------
// FUSED edge kernel. CTA = 128 dst-sorted edges. (R13-proven, unchanged)
// ---------------------------------------------------------------------------
__global__ __launch_bounds__(256) void fused_edge_kernel(
    const float* __restrict__ ea, const float* __restrict__ we)
{
    __shared__ unsigned short Ah[FE_ROWS * 16], Al[FE_ROWS * 16];
    __shared__ unsigned short Bh[HC * 16], Bl[HC * 16];
    __shared__ __half Esm[FE_ROWS * HC];          // 32KB

    int tid = threadIdx.x;
    int e0 = blockIdx.x * FE_ROWS;                // EE % FE_ROWS == 0

    {
        int r = tid >> 1, half = (tid & 1) * 8;
        int eid = g_sde[e0 + r].z;
        float4 v0 = *(const float4*)&ea[(size_t)eid * ED + half];
        float4 v1 = *(const float4*)&ea[(size_t)eid * ED + half + 4];
        float vv[8] = {v0.x, v0.y, v0.z, v0.w, v1.x, v1.y, v1.z, v1.w};
        #pragma unroll
        for (int j = 0; j < 8; j++) {
            __nv_bfloat16 hb = __float2bfloat16(vv[j]);
            __nv_bfloat16 lb = __float2bfloat16(vv[j] - __bfloat162float(hb));
            Ah[r * 16 + half + j] = __bfloat16_as_ushort(hb);
            Al[r * 16 + half + j] = __bfloat16_as_ushort(lb);
        }
    }
    {
        int k = tid >> 4, n0 = (tid & 15) * 8;
        #pragma unroll
        for (int j = 0; j < 8; j++) {
            float v = we[k * HC + n0 + j];
            __nv_bfloat16 hb = __float2bfloat16(v);
            __nv_bfloat16 lb = __float2bfloat16(v - __bfloat162float(hb));
            Bh[(n0 + j) * 16 + k] = __bfloat16_as_ushort(hb);
            Bl[(n0 + j) * 16 + k] = __bfloat16_as_ushort(lb);
        }
    }
    __syncthreads();

    int w = tid >> 5, lane = tid & 31;
    int g = lane >> 2, t = lane & 3;
    int mw = w >> 1, nw = w & 1;

    {
        float acc[2][8][4];
        #pragma unroll
        for (int a = 0; a < 2; a++)
            #pragma unroll
            for (int b = 0; b < 8; b++)
                #pragma unroll
                for (int c = 0; c < 4; c++) acc[a][b][c] = 0.f;

        #pragma unroll
        for (int s = 0; s < 3; s++) {
            const unsigned short* A = (s == 2) ? Al : Ah;
            const unsigned short* B = (s == 1) ? Bl : Bh;
            uint32_t bf[8][2];
            #pragma unroll
            for (int nt = 0; nt < 8; nt++) {
                const unsigned short* p = &B[(nw * 64 + nt * 8 + g) * 16 + t * 2];
                bf[nt][0] = *(const uint32_t*)p;
                bf[nt][1] = *(const uint32_t*)(p + 8);
            }
            #pragma unroll
            for (int mt = 0; mt < 2; mt++) {
                const unsigned short* p = &A[(mw * 32 + mt * 16 + g) * 16 + t * 2];
                uint32_t a0 = *(const uint32_t*)p;
                uint32_t a1 = *(const uint32_t*)(p + 8 * 16);
                uint32_t a2 = *(const uint32_t*)(p + 8);
                uint32_t a3 = *(const uint32_t*)(p + 8 * 16 + 8);
                #pragma unroll
                for (int nt = 0; nt < 8; nt++) {
                    asm volatile(
                        "mma.sync.aligned.m16n8k16.row.col.f32.bf16.bf16.f32 "
                        "{%0,%1,%2,%3}, {%4,%5,%6,%7}, {%8,%9}, {%0,%1,%2,%3};"
                        : "+f"(acc[mt][nt][0]), "+f"(acc[mt][nt][1]),
                          "+f"(acc[mt][nt][2]), "+f"(acc[mt][nt][3])
                        : "r"(a0), "r"(a1), "r"(a2), "r"(a3),
                          "r"(bf[nt][0]), "r"(bf[nt][1]));
                }
            }
        }

        #pragma unroll
        for (int mt = 0; mt < 2; mt++) {
            int r0 = mw * 32 + mt * 16 + g;
            int r1 = r0 + 8;
            #pragma unroll
            for (int nt = 0; nt < 8; nt++) {
                int col = nw * 64 + nt * 8 + t * 2;
                *(__half2*)&Esm[r0 * HC + col] =
                    __floats2half2_rn(acc[mt][nt][0], acc[mt][nt][1]);
                *(__half2*)&Esm[r1 * HC + col] =
                    __floats2half2_rn(acc[mt][nt][2], acc[mt][nt][3]);
            }
        }
    }
    __syncthreads();

    int c0 = lane << 2;
    int head = lane >> 2;
    int lbase = w * 16;
    int gbase = e0 + lbase;

    int cur_dst = -1;
    float4 q4 = make_float4(0.f, 0.f, 0.f, 0.f);
    float nx = 0.f, ny = 0.f, nz = 0.f, nw4 = 0.f, den = 0.f;

    #pragma unroll 4
    for (int i = 0; i < 16; i++) {
        int4 sde = g_sde[gbase + i];
        int src = sde.x, dst = sde.y;

        if (dst != cur_dst) {
            if (cur_dst >= 0) {
                float* op = g_attn + (size_t)cur_dst * HC + c0;
                asm volatile("red.global.add.v4.f32 [%0], {%1, %2, %3, %4};"
                             :: "l"(op), "f"(nx), "f"(ny), "f"(nz), "f"(nw4)
                             : "memory");
                if ((lane & 3) == 0) {
                    float* dp = &g_sum[cur_dst * HH + head];
                    asm volatile("red.global.add.f32 [%0], %1;"
                                 :: "l"(dp), "f"(den) : "memory");
                }
            }
            cur_dst = dst;
            q4 = *(const float4*)&g_q[(size_t)dst * HC + c0];
            nx = ny = nz = nw4 = den = 0.f;
        }

        uint2 eu = *(const uint2*)&Esm[(lbase + i) * HC + c0];
        float2 e01 = __half22float2(*reinterpret_cast<__half2*>(&eu.x));
        float2 e23 = __half22float2(*reinterpret_cast<__half2*>(&eu.y));

        uint2 ku = *(const uint2*)&g_kh[(size_t)src * HC + c0];
        float2 k01 = __half22float2(*reinterpret_cast<__half2*>(&ku.x));
        float2 k23 = __half22float2(*reinterpret_cast<__half2*>(&ku.y));

        float s = q4.x * (k01.x + e01.x) + q4.y * (k01.y + e01.y)
                + q4.z * (k23.x + e23.x) + q4.w * (k23.y + e23.y);
        s += __shfl_xor_sync(0xffffffffu, s, 1);
        s += __shfl_xor_sync(0xffffffffu, s, 2);

        float p = __expf(s * 0.25f);

        uint2 vu = *(const uint2*)&g_vh[(size_t)src * HC + c0];
        float2 v01 = __half22float2(*reinterpret_cast<__half2*>(&vu.x));
        float2 v23 = __half22float2(*reinterpret_cast<__half2*>(&vu.y));

        nx  += (v01.x + e01.x) * p;
        ny  += (v01.y + e01.y) * p;
        nz  += (v23.x + e23.x) * p;
        nw4 += (v23.y + e23.y) * p;
        den += p;
    }

    if (cur_dst >= 0) {
        float* op = g_attn + (size_t)cur_dst * HC + c0;
        asm volatile("red.global.add.v4.f32 [%0], {%1, %2, %3, %4};"
                     :: "l"(op), "f"(nx), "f"(ny), "f"(nz), "f"(nw4)
                     : "memory");
        if ((lane & 3) == 0) {
            float* dp = &g_sum[cur_dst * HH + head];
            asm volatile("red.global.add.f32 [%0], %1;"
                         :: "l"(dp), "f"(den) : "memory");
        }
    }
}

// ---------------------------------------------------------------------------
__global__ __launch_bounds__(256) void normalize_kernel(float* __restrict__ out)
{
    int i = blockIdx.x * blockDim.x + threadIdx.x;
    int n4 = (NN * HC) / 4;
    if (i >= n4) return;
    int node = i >> 5;
    int head = (i & 31) >> 2;
    float inv = 1.f / (g_sum[node * HH + head] + 1e-16f);
    float4 a = ((const float4*)g_attn)[i];
    float4 o = ((float4*)out)[i];
    o.x += a.x * inv; o.y += a.y * inv;
    o.z += a.z * inv; o.w += a.w * inv;
    ((float4*)out)[i] = o;
}

// ---------------------------------------------------------------------------
extern "C" void kernel_launch(void* const* d_in, const int* in_sizes, int n_in,
                              void* d_out, int out_size)
{
    const float* x  = (const float*)d_in[0];
    const int*   ei = (const int*)d_in[1];
    const float* ea = (const float*)d_in[2];
    const float* wq = (const float*)d_in[3];
    const float* bq = (const float*)d_in[4];
    const float* wk = (const float*)d_in[5];
    const float* bk = (const float*)d_in[6];
    const float* wv = (const float*)d_in[7];
    const float* bv = (const float*)d_in[8];
    const float* we = (const float*)d_in[9];
    const float* ws = (const float*)d_in[10];
    const float* bs = (const float*)d_in[11];
    float* out = (float*)d_out;

    // one-time setup (first call = correctness run, outside graph capture)
    static cudaStream_t s1 = nullptr;
    static cudaEvent_t evFork = nullptr, evJoin = nullptr;
    if (!s1) {
        cudaFuncSetAttribute(mma_gemm_kernel,
                             cudaFuncAttributeMaxDynamicSharedMemorySize, SM_TOT);
        cudaStreamCreateWithFlags(&s1, cudaStreamNonBlocking);
        cudaEventCreateWithFlags(&evFork, cudaEventDisableTiming);
        cudaEventCreateWithFlags(&evJoin, cudaEventDisableTiming);
    }

    // fork: side stream s1 runs the CSR chain while the main stream runs
    // the convert+GEMM chain. Join before fused_edge (needs both).
    cudaEventRecord(evFork, 0);
    cudaStreamWaitEvent(s1, evFork, 0);

    // chain A (main stream): projections
    convert_x_kernel<<<((NN * INF) / 4 + 255) / 256, 256>>>(x);
    zero_kernel<<<((NN * HC) / 4 + 255) / 256, 256, 0, s1>>>();
    dim3 gw(64, 4);
    convert_w_kernel<<<gw, 256>>>(wq, wk, wv, ws);
    mma_gemm_kernel<<<391, 256, SM_TOT>>>(bq, bk, bv, bs, out);   // 4th: profiled

    // chain B (s1): CSR build
    hist_kernel<<<(EE + 255) / 256, 256, 0, s1>>>(ei);
    scan1_kernel<<<196, 256, 0, s1>>>();
    scan2_kernel<<<1, 256, 0, s1>>>();
    scan3_kernel<<<NPAD / 256, 256, 0, s1>>>();
    permute_kernel<<<(EE + 255) / 256, 256, 0, s1>>>(ei);
    cudaEventRecord(evJoin, s1);

    // join, then attention + normalize on the main stream
    cudaStreamWaitEvent(0, evJoin, 0);
    fused_edge_kernel<<<EE / FE_ROWS, 256>>>(ea, we);
    normalize_kernel<<<((NN * HC) / 4 + 255) / 256, 256>>>(out);
}